// round 12
// baseline (speedup 1.0000x reference)
#include <cuda_runtime.h>
#include <cuda_bf16.h>

// ---------------------------------------------------------------------------
// SelfAttention2d: N=16, C=512, H=W=64, C_BAR=64, C_HAT=256
// Round 11: identical to Round 8 (infra failure, never benched).
//   1. pack  W_all[384,512]
//   2. proj[n,384,4096] = W_all @ x_n            (tf32 GEMM)
//   3. preps: thetaT[q][dP] bf16, phiT[t][dP] bf16 (pooled), g[c][t] bf16 (pooled)
//   4. flash: yq[n,4096,256] = softmax(theta^T phi) g^T   (fused, q-major out)
//   5. out = gamma * (w_o @ y) + x               (tf32 GEMM, B row-major)
// ---------------------------------------------------------------------------

#define NB    16
#define C_IN  512
#define HWX   4096
#define HW4   1024
#define CBAR  64
#define CHAT  256
#define MPROJ 384

#define BM 128
#define BN 128
#define BK 16
#define ASTR 20
#define BSTR 136

// Scratch (static device globals; no allocation at launch time)
__device__ float         g_Wall[MPROJ * C_IN];
__device__ float         g_proj[(size_t)NB * MPROJ * HWX];
__device__ __nv_bfloat16 g_thetaT[(size_t)NB * HWX * CBAR];  // [b][q][dPerm]
__device__ __nv_bfloat16 g_phiT [(size_t)NB * HW4 * CBAR];   // [b][t][dPerm]
__device__ __nv_bfloat16 g_gbf  [(size_t)NB * CHAT * HW4];   // [b][c][t]
__device__ float         g_yq   [(size_t)NB * HWX * CHAT];   // [b][q][c]

// ---------------------------------------------------------------------------
__device__ __forceinline__ unsigned f2tf(float f) {
    unsigned u;
    asm("cvt.rna.tf32.f32 %0, %1;" : "=r"(u) : "f"(f));
    return u;
}
__device__ __forceinline__ uint4 f2tf4(float4 v) {
    uint4 r; r.x = f2tf(v.x); r.y = f2tf(v.y); r.z = f2tf(v.z); r.w = f2tf(v.w);
    return r;
}
__device__ __forceinline__ void mma_tf32(float d[4], const unsigned a[4],
                                         const unsigned b[2]) {
    asm volatile(
        "mma.sync.aligned.m16n8k8.row.col.f32.tf32.tf32.f32 "
        "{%0,%1,%2,%3}, {%4,%5,%6,%7}, {%8,%9}, {%0,%1,%2,%3};\n"
        : "+f"(d[0]), "+f"(d[1]), "+f"(d[2]), "+f"(d[3])
        : "r"(a[0]), "r"(a[1]), "r"(a[2]), "r"(a[3]), "r"(b[0]), "r"(b[1]));
}
__device__ __forceinline__ void mma_bf16(float d[4], const unsigned a[4],
                                         const unsigned b[2]) {
    asm volatile(
        "mma.sync.aligned.m16n8k16.row.col.f32.bf16.bf16.f32 "
        "{%0,%1,%2,%3}, {%4,%5,%6,%7}, {%8,%9}, {%0,%1,%2,%3};\n"
        : "+f"(d[0]), "+f"(d[1]), "+f"(d[2]), "+f"(d[3])
        : "r"(a[0]), "r"(a[1]), "r"(a[2]), "r"(a[3]), "r"(b[0]), "r"(b[1]));
}

// Inverse interleave permutation (within 16-blocks): phys col p holds logical
// index lam(p).
__device__ __forceinline__ int lam(int p) {
    int blk = p & ~15, w = p & 15, pp = w >> 1, bb = w & 1;
    return blk + 2 * ((pp >> 1) + (pp & 1) * 4) + bb;
}

// ---------------------------------------------------------------------------
// Flash attention: 256 threads, MQ=64 queries/CTA, 8 KV tiles of 128.
// QK bf16 (m16n8k16), no-max softmax, PV bf16 with V direct from gmem.
// ---------------------------------------------------------------------------
#define MQF   64
#define QSTRf 80
#define KSTRf 80
#define PSTRf 144
#define FL_SMEM (64*QSTRf*2 + 128*KSTRf*2 + 64*PSTRf*2 + 1024)  // 50176

__global__ __launch_bounds__(256, 2) void flash_kernel()
{
    extern __shared__ char smc[];
    __nv_bfloat16* Qs  = (__nv_bfloat16*)smc;               // [64][80]
    __nv_bfloat16* Ks  = (__nv_bfloat16*)(smc + 10240);     // [128][80] (perm rows)
    __nv_bfloat16* Ps  = (__nv_bfloat16*)(smc + 30720);     // [64][144] (perm cols)
    float*         red = (float*)(smc + 49152);             // [4][64]

    const int tid  = threadIdx.x;
    const int lane = tid & 31;
    const int warp = tid >> 5;
    const int g    = lane >> 2;
    const int tig  = lane & 3;
    const int wr   = warp & 1;
    const int wc   = warp >> 1;

    const int b  = blockIdx.y;
    const int q0 = blockIdx.x * MQF;

    const __nv_bfloat16* thT = g_thetaT + ((long)b * HWX + q0) * CBAR;
    const __nv_bfloat16* phT = g_phiT + (long)b * HW4 * CBAR;
    const __nv_bfloat16* gb  = g_gbf  + (long)b * CHAT * HW4;
    float*               yq  = g_yq   + (long)b * HWX * CHAT;

    // Q tile copy (once): 64 rows x 64 bf16 = 512 uint4 (full coverage).
#pragma unroll
    for (int i = 0; i < 2; i++) {
        int idx = tid + i * 256;
        int r = idx >> 3, seg = idx & 7;
        *(uint4*)(Qs + r * QSTRf + seg * 8) =
            *(const uint4*)(thT + r * CBAR + seg * 8);
    }

    float acc_o[2][8][4];
    float ls[4] = {0.f, 0.f, 0.f, 0.f};
#pragma unroll
    for (int mi = 0; mi < 2; mi++)
#pragma unroll
        for (int ni = 0; ni < 8; ni++)
#pragma unroll
            for (int e = 0; e < 4; e++) acc_o[mi][ni][e] = 0.f;

    // K tile LDG: 128 rows x 64 bf16 = 1024 x 16B; 4 per thread.
    // Row r (tile position) sources gmem t = t0 + gamma(r).
    uint4 kreg[4];
    int   ksrc[4];
#pragma unroll
    for (int i = 0; i < 4; i++) {
        int idx = tid + i * 256, r = idx >> 3;
        int w = r & 15, p = w >> 1, bb = w & 1;
        ksrc[i] = (r & ~15) + (p < 4 ? 4 * p + bb : 4 * (p - 4) + 2 + bb);
    }
    auto ldgK = [&](int t0) {
#pragma unroll
        for (int i = 0; i < 4; i++) {
            int idx = tid + i * 256, seg = idx & 7;
            kreg[i] = *(const uint4*)(phT + (long)(t0 + ksrc[i]) * CBAR + seg * 8);
        }
    };

    ldgK(0);

#pragma unroll 1
    for (int j = 0; j < 8; j++) {
        const int t0 = j * 128;
        __syncthreads();                       // Ks & Ps writable
#pragma unroll
        for (int i = 0; i < 4; i++) {
            int idx = tid + i * 256, r = idx >> 3, seg = idx & 7;
            *(uint4*)(Ks + r * KSTRf + seg * 8) = kreg[i];
        }
        __syncthreads();                       // Ks (and Qs on j==0) visible

        // ---- S = Q K^T (bf16) ----
        float acc_s[2][4][4];
#pragma unroll
        for (int mi = 0; mi < 2; mi++)
#pragma unroll
            for (int ni = 0; ni < 4; ni++)
#pragma unroll
                for (int e = 0; e < 4; e++) acc_s[mi][ni][e] = 0.f;

#pragma unroll
        for (int kb = 0; kb < 4; kb++) {
            unsigned af[2][4], bfr[4][2];
#pragma unroll
            for (int mi = 0; mi < 2; mi++) {
                const __nv_bfloat16* ba =
                    Qs + (wr * 32 + mi * 16 + g) * QSTRf + kb * 16 + 4 * tig;
                uint2 lo = *(const uint2*)ba;
                uint2 hi = *(const uint2*)(ba + 8 * QSTRf);
                af[mi][0] = lo.x; af[mi][1] = hi.x;
                af[mi][2] = lo.y; af[mi][3] = hi.y;
            }
#pragma unroll
            for (int ni = 0; ni < 4; ni++) {
                uint2 kv = *(const uint2*)(Ks + (wc * 32 + ni * 8 + g) * KSTRf
                                           + kb * 16 + 4 * tig);
                bfr[ni][0] = kv.x; bfr[ni][1] = kv.y;
            }
#pragma unroll
            for (int mi = 0; mi < 2; mi++)
#pragma unroll
                for (int ni = 0; ni < 4; ni++)
                    mma_bf16(acc_s[mi][ni], af[mi], bfr[ni]);
        }

        // ---- P = exp(S) (no max), accumulate sums, store P bf16 (perm cols) ----
#pragma unroll
        for (int mi = 0; mi < 2; mi++)
#pragma unroll
            for (int ni = 0; ni < 4; ni++) {
                float p0 = __expf(acc_s[mi][ni][0]);
                float p1 = __expf(acc_s[mi][ni][1]);
                float p2 = __expf(acc_s[mi][ni][2]);
                float p3 = __expf(acc_s[mi][ni][3]);
                ls[mi * 2 + 0] += p0 + p1;
                ls[mi * 2 + 1] += p2 + p3;
                int colp = wc * 32 + (ni >> 1) * 16 + 4 * tig + (ni & 1) * 2;
                int q = wr * 32 + mi * 16 + g;
                *(__nv_bfloat162*)(Ps + q * PSTRf + colp) =
                    __float22bfloat162_rn(make_float2(p0, p1));
                *(__nv_bfloat162*)(Ps + (q + 8) * PSTRf + colp) =
                    __float22bfloat162_rn(make_float2(p2, p3));
            }
        __syncthreads();                       // Ps visible

        // ---- O += P V  (V straight from gmem, 8B coalesced via perm) ----
#pragma unroll
        for (int kt = 0; kt < 8; kt++) {
            unsigned pa[2][4];
#pragma unroll
            for (int mi = 0; mi < 2; mi++) {
                const __nv_bfloat16* bp =
                    Ps + (wr * 32 + mi * 16 + g) * PSTRf + kt * 16 + 4 * tig;
                uint2 lo = *(const uint2*)bp;
                uint2 hi = *(const uint2*)(bp + 8 * PSTRf);
                pa[mi][0] = lo.x; pa[mi][1] = hi.x;
                pa[mi][2] = lo.y; pa[mi][3] = hi.y;
            }
#pragma unroll
            for (int ni = 0; ni < 8; ni++) {
                int c = wc * 64 + ni * 8 + g;
                uint2 vv = *(const uint2*)(gb + (long)c * HW4 + t0
                                           + kt * 16 + 4 * tig);
                unsigned vr[2] = {vv.x, vv.y};
                mma_bf16(acc_o[0][ni], pa[0], vr);
                mma_bf16(acc_o[1][ni], pa[1], vr);
            }
        }
        if (j < 7) ldgK(t0 + 128);
    }

    // ---- final row-sum reduction & y write (q-major) ----
#pragma unroll
    for (int r = 0; r < 4; r++) {
        ls[r] += __shfl_xor_sync(0xffffffffu, ls[r], 1);
        ls[r] += __shfl_xor_sync(0xffffffffu, ls[r], 2);
    }
    if (tig == 0) {
#pragma unroll
        for (int r = 0; r < 4; r++) {
            int row = wr * 32 + (r >> 1) * 16 + (r & 1) * 8 + g;
            red[wc * 64 + row] = ls[r];
        }
    }
    __syncthreads();
    float inv[4];
#pragma unroll
    for (int r = 0; r < 4; r++) {
        int row = wr * 32 + (r >> 1) * 16 + (r & 1) * 8 + g;
        float l = red[row] + red[64 + row] + red[128 + row] + red[192 + row];
        inv[r] = 1.0f / l;
    }
#pragma unroll
    for (int mi = 0; mi < 2; mi++) {
        int q = q0 + wr * 32 + mi * 16 + g;
#pragma unroll
        for (int ni = 0; ni < 8; ni++) {
            int c = wc * 64 + ni * 8 + 2 * tig;
            float2 v0 = make_float2(acc_o[mi][ni][0] * inv[mi * 2 + 0],
                                    acc_o[mi][ni][1] * inv[mi * 2 + 0]);
            float2 v1 = make_float2(acc_o[mi][ni][2] * inv[mi * 2 + 1],
                                    acc_o[mi][ni][3] * inv[mi * 2 + 1]);
            *(float2*)(yq + (long)q * CHAT + c)       = v0;
            *(float2*)(yq + (long)(q + 8) * CHAT + c) = v1;
        }
    }
}

// ---------------------------------------------------------------------------
// tf32 GEMM: C = A @ B (+ gamma/residual).  A row-major [M,K].
// LAYB=0: B k-major [K,N]. LAYB=1: B row-major [N,K] (ldb=K).
// ---------------------------------------------------------------------------
template<int LAYB, int EPI>
__global__ __launch_bounds__(256, 2) void gemm_tc(
    const float* __restrict__ A, const float* __restrict__ B,
    float* __restrict__ C,
    int N, int K, int lda, int ldb,
    long sA, long sB, long sC,
    const float* __restrict__ gammaPtr,
    const float* __restrict__ resid, long sR)
{
    __shared__ __align__(16) unsigned As[2][BM][ASTR];
    __shared__ __align__(16) unsigned Bs[2][BK][BSTR];

    const int tid  = threadIdx.x;
    const int lane = tid & 31;
    const int warp = tid >> 5;
    const int g    = lane >> 2;
    const int tig  = lane & 3;
    const int wm   = (warp & 1) * 64;
    const int wn   = (warp >> 1) * 32;

    const int b  = blockIdx.z;
    const int m0 = blockIdx.y * BM;
    const int n0 = blockIdx.x * BN;

    const float* Ap = A + (long)b * sA;
    const float* Bp = B + (long)b * sB;
    float*       Cp = C + (long)b * sC;

    float acc[4][4][4];
#pragma unroll
    for (int i = 0; i < 4; i++)
#pragma unroll
        for (int j = 0; j < 4; j++)
#pragma unroll
            for (int r = 0; r < 4; r++) acc[i][j][r] = 0.f;

    float4 ra0, ra1, rb0, rb1;

    auto loadA = [&](int k0) {
        int m = tid >> 2, kq = (tid & 3) << 2;
        ra0 = *(const float4*)(Ap + (long)(m0 + m)      * lda + k0 + kq);
        ra1 = *(const float4*)(Ap + (long)(m0 + m + 64) * lda + k0 + kq);
    };
    auto loadB = [&](int k0) {
        if (LAYB == 0) {
            int k = tid >> 5, n = (tid & 31) << 2;
            rb0 = *(const float4*)(Bp + (long)(k0 + k)     * ldb + n0 + n);
            rb1 = *(const float4*)(Bp + (long)(k0 + k + 8) * ldb + n0 + n);
        } else {
            int n = tid >> 2, kq = (tid & 3) << 2;
            rb0 = *(const float4*)(Bp + (long)(n0 + n)      * ldb + k0 + kq);
            rb1 = *(const float4*)(Bp + (long)(n0 + n + 64) * ldb + k0 + kq);
        }
    };
    auto storeAB = [&](int buf) {
        int m = tid >> 2, kq = (tid & 3) << 2;
        *(uint4*)&As[buf][m][kq]      = f2tf4(ra0);
        *(uint4*)&As[buf][m + 64][kq] = f2tf4(ra1);
        if (LAYB == 0) {
            int k = tid >> 5, n = (tid & 31) << 2;
            int s0 = ((k >> 2) & 3) << 3;
            int s1 = (((k + 8) >> 2) & 3) << 3;
            *(uint4*)&Bs[buf][k][n ^ s0]     = f2tf4(rb0);
            *(uint4*)&Bs[buf][k + 8][n ^ s1] = f2tf4(rb1);
        } else {
            int n = tid >> 2, q = tid & 3;
            int s  = q << 3;
            int c0 = n ^ s, c1 = (n + 64) ^ s;
            Bs[buf][4 * q + 0][c0] = f2tf(rb0.x);
            Bs[buf][4 * q + 1][c0] = f2tf(rb0.y);
            Bs[buf][4 * q + 2][c0] = f2tf(rb0.z);
            Bs[buf][4 * q + 3][c0] = f2tf(rb0.w);
            Bs[buf][4 * q + 0][c1] = f2tf(rb1.x);
            Bs[buf][4 * q + 1][c1] = f2tf(rb1.y);
            Bs[buf][4 * q + 2][c1] = f2tf(rb1.z);
            Bs[buf][4 * q + 3][c1] = f2tf(rb1.w);
        }
    };
    auto compute = [&](int buf) {
#pragma unroll
        for (int ks = 0; ks < BK; ks += 8) {
            unsigned af[4][4], bfr[4][2];
            const int s0 = ((ks >> 2) & 3) << 3;
            const int s1 = (((ks >> 2) + 1) & 3) << 3;
#pragma unroll
            for (int mi = 0; mi < 4; mi++) {
                int m = wm + mi * 16;
                af[mi][0] = As[buf][m + g]    [ks + tig];
                af[mi][1] = As[buf][m + g + 8][ks + tig];
                af[mi][2] = As[buf][m + g]    [ks + tig + 4];
                af[mi][3] = As[buf][m + g + 8][ks + tig + 4];
            }
#pragma unroll
            for (int ni = 0; ni < 4; ni++) {
                int n = wn + ni * 8 + g;
                bfr[ni][0] = Bs[buf][ks + tig]    [n ^ s0];
                bfr[ni][1] = Bs[buf][ks + tig + 4][n ^ s1];
            }
#pragma unroll
            for (int mi = 0; mi < 4; mi++)
#pragma unroll
                for (int ni = 0; ni < 4; ni++)
                    mma_tf32(acc[mi][ni], af[mi], bfr[ni]);
        }
    };

    const int nt = K / BK;
    loadA(0); loadB(0);
    storeAB(0);
    __syncthreads();
#pragma unroll 1
    for (int t = 0; t < nt; t++) {
        if (t + 1 < nt) { loadA((t + 1) * BK); loadB((t + 1) * BK); }
        compute(t & 1);
        if (t + 1 < nt) storeAB((t + 1) & 1);
        __syncthreads();
    }

    float gam = 0.f;
    const float* Rp = nullptr;
    if (EPI) { gam = gammaPtr[0]; Rp = resid + (long)b * sR; }

#pragma unroll
    for (int mi = 0; mi < 4; mi++) {
#pragma unroll
        for (int ni = 0; ni < 4; ni++) {
            int m = m0 + wm + mi * 16 + g;
            int n = n0 + wn + ni * 8 + 2 * tig;
            float2 v0 = make_float2(acc[mi][ni][0], acc[mi][ni][1]);
            float2 v1 = make_float2(acc[mi][ni][2], acc[mi][ni][3]);
            if (EPI) {
                float2 r0 = *(const float2*)(Rp + (long)m * N + n);
                float2 r1 = *(const float2*)(Rp + (long)(m + 8) * N + n);
                v0.x = fmaf(gam, v0.x, r0.x);
                v0.y = fmaf(gam, v0.y, r0.y);
                v1.x = fmaf(gam, v1.x, r1.x);
                v1.y = fmaf(gam, v1.y, r1.y);
            }
            *(float2*)(Cp + (long)m * N + n)       = v0;
            *(float2*)(Cp + (long)(m + 8) * N + n) = v1;
        }
    }
}

// ---------------------------------------------------------------------------
__global__ void pack_w_kernel(const float* __restrict__ wt,
                              const float* __restrict__ wp,
                              const float* __restrict__ wg)
{
    int i = blockIdx.x * blockDim.x + threadIdx.x;
    if (i >= MPROJ * C_IN) return;
    const int T = 64 * C_IN;
    const int P = 128 * C_IN;
    float v;
    if (i < T)       v = wt[i];
    else if (i < P)  v = wp[i - T];
    else             v = wg[i - P];
    g_Wall[i] = v;
}

// thetaT[b][q][p] = bf16(theta[lam(p)][q])   (64 x 64 tiles via smem)
__global__ __launch_bounds__(256) void theta_prep()
{
    __shared__ float sm[64][65];
    int b = blockIdx.y, q0 = blockIdx.x * 64;
    int tid = threadIdx.x;
    const float* src = g_proj + (long)b * MPROJ * HWX;
#pragma unroll
    for (int i = 0; i < 4; i++) {
        int idx = tid + i * 256;
        int d = idx >> 4, q4 = (idx & 15) * 4;
        float4 v = *(const float4*)(src + (long)d * HWX + q0 + q4);
        sm[d][q4] = v.x; sm[d][q4 + 1] = v.y;
        sm[d][q4 + 2] = v.z; sm[d][q4 + 3] = v.w;
    }
    __syncthreads();
    __nv_bfloat16* dst = g_thetaT + ((long)b * HWX + q0) * CBAR;
#pragma unroll
    for (int i = 0; i < 4; i++) {
        int idx = tid + i * 256;
        int q = idx >> 4, p4 = (idx & 15) * 4;
        *(__nv_bfloat162*)(dst + (long)q * CBAR + p4) =
            __float22bfloat162_rn(make_float2(sm[lam(p4)][q], sm[lam(p4 + 1)][q]));
        *(__nv_bfloat162*)(dst + (long)q * CBAR + p4 + 2) =
            __float22bfloat162_rn(make_float2(sm[lam(p4 + 2)][q], sm[lam(p4 + 3)][q]));
    }
}

// phiT[b][t][p] = bf16(maxpool(phi)[lam(p)][t])
__global__ __launch_bounds__(256) void phi_prep()
{
    __shared__ float sm[64][65];
    int b = blockIdx.y, t0 = blockIdx.x * 64;
    int tid = threadIdx.x;
    const float* src = g_proj + ((long)b * MPROJ + 64) * HWX;
#pragma unroll
    for (int i = 0; i < 16; i++) {
        int idx = tid + i * 256;
        int d = idx >> 6, t = idx & 63;
        int tt = t0 + t, ph = tt >> 5, pw = tt & 31;
        const float* p = src + (long)d * HWX + ph * 128 + 2 * pw;
        sm[d][t] = fmaxf(fmaxf(p[0], p[1]), fmaxf(p[64], p[65]));
    }
    __syncthreads();
    __nv_bfloat16* dst = g_phiT + ((long)b * HW4 + t0) * CBAR;
#pragma unroll
    for (int i = 0; i < 4; i++) {
        int idx = tid + i * 256;
        int t = idx >> 4, p4 = (idx & 15) * 4;
        *(__nv_bfloat162*)(dst + (long)t * CBAR + p4) =
            __float22bfloat162_rn(make_float2(sm[lam(p4)][t], sm[lam(p4 + 1)][t]));
        *(__nv_bfloat162*)(dst + (long)t * CBAR + p4 + 2) =
            __float22bfloat162_rn(make_float2(sm[lam(p4 + 2)][t], sm[lam(p4 + 3)][t]));
    }
}

// g_gbf[b][c][t] = bf16(maxpool(g)[c][t])
__global__ __launch_bounds__(256) void g_prep()
{
    int idx = blockIdx.x * 256 + threadIdx.x;
    int t = idx & 1023;
    int c = (idx >> 10) & 255;
    int b = idx >> 18;
    const float* src = g_proj + ((long)b * MPROJ + 128 + c) * HWX;
    int ph = t >> 5, pw = t & 31;
    const float* p = src + ph * 128 + 2 * pw;
    float m = fmaxf(fmaxf(p[0], p[1]), fmaxf(p[64], p[65]));
    g_gbf[idx] = __float2bfloat16(m);
}

// ---------------------------------------------------------------------------
extern "C" void kernel_launch(void* const* d_in, const int* in_sizes, int n_in,
                              void* d_out, int out_size)
{
    const float* x       = (const float*)d_in[0];
    const float* w_theta = (const float*)d_in[1];
    const float* w_phi   = (const float*)d_in[2];
    const float* w_g     = (const float*)d_in[3];
    const float* w_o     = (const float*)d_in[4];
    const float* gamma   = (const float*)d_in[5];
    float* out = (float*)d_out;

    float *pWall, *pProj, *pYq;
    cudaGetSymbolAddress((void**)&pWall, g_Wall);
    cudaGetSymbolAddress((void**)&pProj, g_proj);
    cudaGetSymbolAddress((void**)&pYq,   g_yq);

    static int smem_set = 0;
    if (!smem_set) {
        cudaFuncSetAttribute(flash_kernel,
                             cudaFuncAttributeMaxDynamicSharedMemorySize,
                             FL_SMEM);
        smem_set = 1;
    }

    // 1. pack weights
    pack_w_kernel<<<(MPROJ * C_IN + 255) / 256, 256>>>(w_theta, w_phi, w_g);

    // 2. proj = W_all @ x : M=384, N=4096, K=512
    {
        dim3 grid(HWX / BN, MPROJ / BM, NB);
        gemm_tc<0, 0><<<grid, 256>>>(pWall, x, pProj,
                                     HWX, C_IN, C_IN, HWX,
                                     0, (long)C_IN * HWX, (long)MPROJ * HWX,
                                     nullptr, nullptr, 0);
    }

    // 3. preps: thetaT / phiT (pooled) / g bf16 (pooled)
    theta_prep<<<dim3(HWX / 64, NB), 256>>>();
    phi_prep<<<dim3(HW4 / 64, NB), 256>>>();
    g_prep<<<(NB * CHAT * HW4) / 256, 256>>>();

    // 4. flash: fused scores -> softmax -> y  (q-major output)
    {
        dim3 grid(HWX / MQF, NB);
        flash_kernel<<<grid, 256, FL_SMEM>>>();
    }

    // 5. out = gamma * (w_o @ y) + x : M=512, N=4096, K=256, B row-major [q][c]
    {
        dim3 grid(HWX / BN, C_IN / BM, NB);
        gemm_tc<1, 1><<<grid, 256>>>(w_o, pYq, out,
                                     HWX, CHAT, CHAT, CHAT,
                                     0, (long)HWX * CHAT, (long)C_IN * HWX,
                                     gamma, x, (long)C_IN * HWX);
    }
}

// round 17
// speedup vs baseline: 1.2994x; 1.2994x over previous
#include <cuda_runtime.h>
#include <cuda_bf16.h>

// ---------------------------------------------------------------------------
// SelfAttention2d: N=16, C=512, H=W=64, C_BAR=64, C_HAT=256
// Round 15: R13 with the V smem copy fixed (it covered only half the tile
// columns -> uninitialized smem in PV -> NaN; same bug class as R8's Q copy).
//   1. pack  W_all[384,512]
//   2. proj[n,384,4096] = W_all @ x_n            (tf32 GEMM)
//   3. preps: thetaT[q][dP] bf16, phiT[t][dP] bf16 (pooled), g[c][t] bf16 (pooled)
//   4. flash: yq[n,4096,256] = softmax(theta^T phi) g^T   (fused, q-major out)
//   5. out = gamma * (w_o @ y) + x               (tf32 GEMM, B row-major)
// ---------------------------------------------------------------------------

#define NB    16
#define C_IN  512
#define HWX   4096
#define HW4   1024
#define CBAR  64
#define CHAT  256
#define MPROJ 384

#define BM 128
#define BN 128
#define BK 16
#define ASTR 20
#define BSTR 136

// Scratch (static device globals; no allocation at launch time)
__device__ float         g_Wall[MPROJ * C_IN];
__device__ float         g_proj[(size_t)NB * MPROJ * HWX];
__device__ __nv_bfloat16 g_thetaT[(size_t)NB * HWX * CBAR];  // [b][q][dPerm]
__device__ __nv_bfloat16 g_phiT [(size_t)NB * HW4 * CBAR];   // [b][t][dPerm]
__device__ __nv_bfloat16 g_gbf  [(size_t)NB * CHAT * HW4];   // [b][c][t]
__device__ float         g_yq   [(size_t)NB * HWX * CHAT];   // [b][q][c]

// ---------------------------------------------------------------------------
__device__ __forceinline__ unsigned f2tf(float f) {
    unsigned u;
    asm("cvt.rna.tf32.f32 %0, %1;" : "=r"(u) : "f"(f));
    return u;
}
__device__ __forceinline__ uint4 f2tf4(float4 v) {
    uint4 r; r.x = f2tf(v.x); r.y = f2tf(v.y); r.z = f2tf(v.z); r.w = f2tf(v.w);
    return r;
}
__device__ __forceinline__ void mma_tf32(float d[4], const unsigned a[4],
                                         const unsigned b[2]) {
    asm volatile(
        "mma.sync.aligned.m16n8k8.row.col.f32.tf32.tf32.f32 "
        "{%0,%1,%2,%3}, {%4,%5,%6,%7}, {%8,%9}, {%0,%1,%2,%3};\n"
        : "+f"(d[0]), "+f"(d[1]), "+f"(d[2]), "+f"(d[3])
        : "r"(a[0]), "r"(a[1]), "r"(a[2]), "r"(a[3]), "r"(b[0]), "r"(b[1]));
}
__device__ __forceinline__ void mma_bf16(float d[4], const unsigned a[4],
                                         const unsigned b[2]) {
    asm volatile(
        "mma.sync.aligned.m16n8k16.row.col.f32.bf16.bf16.f32 "
        "{%0,%1,%2,%3}, {%4,%5,%6,%7}, {%8,%9}, {%0,%1,%2,%3};\n"
        : "+f"(d[0]), "+f"(d[1]), "+f"(d[2]), "+f"(d[3])
        : "r"(a[0]), "r"(a[1]), "r"(a[2]), "r"(a[3]), "r"(b[0]), "r"(b[1]));
}

// Inverse interleave permutation (within 16-blocks): phys col p holds logical
// index lam(p).
__device__ __forceinline__ int lam(int p) {
    int blk = p & ~15, w = p & 15, pp = w >> 1, bb = w & 1;
    return blk + 2 * ((pp >> 1) + (pp & 1) * 4) + bb;
}

// ---------------------------------------------------------------------------
// Flash attention: 512 threads, MQ=128 queries/CTA, 8 KV tiles of 128.
// QK bf16 (m16n8k16), no-max softmax, V staged in smem (bf16).
// Warps: wr = warp&3 (q 32-row group), wc = warp>>2 (t group QK / c group PV).
// ---------------------------------------------------------------------------
#define MQF   128
#define QST   80
#define KST   80
#define VST   144
#define PST   144
#define FL_SMEM (128*QST*2 + 128*KST*2 + 256*VST*2 + 128*PST*2 + 2048) // 153600

__global__ __launch_bounds__(512, 1) void flash_kernel()
{
    extern __shared__ char smc[];
    __nv_bfloat16* Qs  = (__nv_bfloat16*)smc;                 // [128][80]
    __nv_bfloat16* Ks  = (__nv_bfloat16*)(smc + 20480);       // [128][80] (perm rows)
    __nv_bfloat16* Vs  = (__nv_bfloat16*)(smc + 40960);       // [256][144]
    __nv_bfloat16* Ps  = (__nv_bfloat16*)(smc + 114688);      // [128][144] (perm cols)
    float*         red = (float*)(smc + 151552);              // [4][128]

    const int tid  = threadIdx.x;
    const int lane = tid & 31;
    const int warp = tid >> 5;
    const int g    = lane >> 2;
    const int tig  = lane & 3;
    const int wr   = warp & 3;
    const int wc   = warp >> 2;

    const int b  = blockIdx.y;
    const int q0 = blockIdx.x * MQF;

    const __nv_bfloat16* thT = g_thetaT + ((long)b * HWX + q0) * CBAR;
    const __nv_bfloat16* phT = g_phiT + (long)b * HW4 * CBAR;
    const __nv_bfloat16* gb  = g_gbf  + (long)b * CHAT * HW4;
    float*               yq  = g_yq   + (long)b * HWX * CHAT;

    // Q tile copy (once): 128 rows x 64 bf16 = 1024 uint4, 2/thread.
#pragma unroll
    for (int i = 0; i < 2; i++) {
        int idx = tid + i * 512;
        int r = idx >> 3, seg = idx & 7;
        *(uint4*)(Qs + r * QST + seg * 8) =
            *(const uint4*)(thT + r * CBAR + seg * 8);
    }

    float acc_o[2][8][4];
    float ls[4] = {0.f, 0.f, 0.f, 0.f};
#pragma unroll
    for (int mi = 0; mi < 2; mi++)
#pragma unroll
        for (int ni = 0; ni < 8; ni++)
#pragma unroll
            for (int e = 0; e < 4; e++) acc_o[mi][ni][e] = 0.f;

    // K tile LDG prefetch: 128 rows x 64 bf16 = 1024 x 16B; 2/thread.
    // Tile row r sources gmem t = t0 + gamma(r) (interleave perm).
    uint4 kreg[2];
    int   ksrc[2];
#pragma unroll
    for (int i = 0; i < 2; i++) {
        int idx = tid + i * 512, r = idx >> 3;
        int w = r & 15, p = w >> 1, bb = w & 1;
        ksrc[i] = (r & ~15) + (p < 4 ? 4 * p + bb : 4 * (p - 4) + 2 + bb);
    }
    auto ldgK = [&](int t0) {
#pragma unroll
        for (int i = 0; i < 2; i++) {
            int idx = tid + i * 512, seg = idx & 7;
            kreg[i] = *(const uint4*)(phT + (long)(t0 + ksrc[i]) * CBAR + seg * 8);
        }
    };

    ldgK(0);

#pragma unroll 1
    for (int j = 0; j < 8; j++) {
        const int t0 = j * 128;
        __syncthreads();                       // Ks/Vs/Ps writable
        // store prefetched K
#pragma unroll
        for (int i = 0; i < 2; i++) {
            int idx = tid + i * 512, r = idx >> 3, seg = idx & 7;
            *(uint4*)(Ks + r * KST + seg * 8) = kreg[i];
        }
        // V tile copy: 256 rows x 128 bf16 = 4096 uint4, 8/thread (linear t).
        // (FIXED: was 2048 chunks / half coverage -> NaN)
#pragma unroll
        for (int i = 0; i < 8; i++) {
            int idx = tid + i * 512, c = idx >> 4, seg = idx & 15;
            *(uint4*)(Vs + c * VST + seg * 8) =
                *(const uint4*)(gb + (long)c * HW4 + t0 + seg * 8);
        }
        __syncthreads();                       // tiles visible

        // ---- S = Q K^T (bf16) : warp tile [32 q] x [32 t] ----
        float acc_s[2][4][4];
#pragma unroll
        for (int mi = 0; mi < 2; mi++)
#pragma unroll
            for (int ni = 0; ni < 4; ni++)
#pragma unroll
                for (int e = 0; e < 4; e++) acc_s[mi][ni][e] = 0.f;

#pragma unroll
        for (int kb = 0; kb < 4; kb++) {
            unsigned af[2][4], bfr[4][2];
#pragma unroll
            for (int mi = 0; mi < 2; mi++) {
                const __nv_bfloat16* ba =
                    Qs + (wr * 32 + mi * 16 + g) * QST + kb * 16 + 4 * tig;
                uint2 lo = *(const uint2*)ba;
                uint2 hi = *(const uint2*)(ba + 8 * QST);
                af[mi][0] = lo.x; af[mi][1] = hi.x;
                af[mi][2] = lo.y; af[mi][3] = hi.y;
            }
#pragma unroll
            for (int ni = 0; ni < 4; ni++) {
                uint2 kv = *(const uint2*)(Ks + (wc * 32 + ni * 8 + g) * KST
                                           + kb * 16 + 4 * tig);
                bfr[ni][0] = kv.x; bfr[ni][1] = kv.y;
            }
#pragma unroll
            for (int mi = 0; mi < 2; mi++)
#pragma unroll
                for (int ni = 0; ni < 4; ni++)
                    mma_bf16(acc_s[mi][ni], af[mi], bfr[ni]);
        }

        // ---- P = exp(S) (no max), accumulate sums, store P bf16 (perm cols) ----
#pragma unroll
        for (int mi = 0; mi < 2; mi++)
#pragma unroll
            for (int ni = 0; ni < 4; ni++) {
                float p0 = __expf(acc_s[mi][ni][0]);
                float p1 = __expf(acc_s[mi][ni][1]);
                float p2 = __expf(acc_s[mi][ni][2]);
                float p3 = __expf(acc_s[mi][ni][3]);
                ls[mi * 2 + 0] += p0 + p1;
                ls[mi * 2 + 1] += p2 + p3;
                int colp = wc * 32 + (ni >> 1) * 16 + 4 * tig + (ni & 1) * 2;
                int q = wr * 32 + mi * 16 + g;
                *(__nv_bfloat162*)(Ps + q * PST + colp) =
                    __float22bfloat162_rn(make_float2(p0, p1));
                *(__nv_bfloat162*)(Ps + (q + 8) * PST + colp) =
                    __float22bfloat162_rn(make_float2(p2, p3));
            }
        __syncthreads();                       // Ps visible

        // ---- O += P V : warp tile [32 q] x [64 c], V from smem ----
#pragma unroll
        for (int kt = 0; kt < 8; kt++) {
            unsigned pa[2][4];
#pragma unroll
            for (int mi = 0; mi < 2; mi++) {
                const __nv_bfloat16* bp =
                    Ps + (wr * 32 + mi * 16 + g) * PST + kt * 16 + 4 * tig;
                uint2 lo = *(const uint2*)bp;
                uint2 hi = *(const uint2*)(bp + 8 * PST);
                pa[mi][0] = lo.x; pa[mi][1] = hi.x;
                pa[mi][2] = lo.y; pa[mi][3] = hi.y;
            }
#pragma unroll
            for (int ni = 0; ni < 8; ni++) {
                int c = wc * 64 + ni * 8 + g;
                uint2 vv = *(const uint2*)(Vs + c * VST + kt * 16 + 4 * tig);
                unsigned vr[2] = {vv.x, vv.y};
                mma_bf16(acc_o[0][ni], pa[0], vr);
                mma_bf16(acc_o[1][ni], pa[1], vr);
            }
        }
        if (j < 7) ldgK(t0 + 128);
    }

    // ---- final row-sum reduction & y write (q-major) ----
#pragma unroll
    for (int r = 0; r < 4; r++) {
        ls[r] += __shfl_xor_sync(0xffffffffu, ls[r], 1);
        ls[r] += __shfl_xor_sync(0xffffffffu, ls[r], 2);
    }
    if (tig == 0) {
#pragma unroll
        for (int r = 0; r < 4; r++) {
            int row = wr * 32 + (r >> 1) * 16 + (r & 1) * 8 + g;
            red[wc * 128 + row] = ls[r];
        }
    }
    __syncthreads();
    float inv[4];
#pragma unroll
    for (int r = 0; r < 4; r++) {
        int row = wr * 32 + (r >> 1) * 16 + (r & 1) * 8 + g;
        float l = red[row] + red[128 + row] + red[256 + row] + red[384 + row];
        inv[r] = 1.0f / l;
    }
#pragma unroll
    for (int mi = 0; mi < 2; mi++) {
        int q = q0 + wr * 32 + mi * 16 + g;
#pragma unroll
        for (int ni = 0; ni < 8; ni++) {
            int c = wc * 64 + ni * 8 + 2 * tig;
            float2 v0 = make_float2(acc_o[mi][ni][0] * inv[mi * 2 + 0],
                                    acc_o[mi][ni][1] * inv[mi * 2 + 0]);
            float2 v1 = make_float2(acc_o[mi][ni][2] * inv[mi * 2 + 1],
                                    acc_o[mi][ni][3] * inv[mi * 2 + 1]);
            *(float2*)(yq + (long)q * CHAT + c)       = v0;
            *(float2*)(yq + (long)(q + 8) * CHAT + c) = v1;
        }
    }
}

// ---------------------------------------------------------------------------
// tf32 GEMM: C = A @ B (+ gamma/residual).  A row-major [M,K].
// LAYB=0: B k-major [K,N]. LAYB=1: B row-major [N,K] (ldb=K).
// ---------------------------------------------------------------------------
template<int LAYB, int EPI>
__global__ __launch_bounds__(256, 2) void gemm_tc(
    const float* __restrict__ A, const float* __restrict__ B,
    float* __restrict__ C,
    int N, int K, int lda, int ldb,
    long sA, long sB, long sC,
    const float* __restrict__ gammaPtr,
    const float* __restrict__ resid, long sR)
{
    __shared__ __align__(16) unsigned As[2][BM][ASTR];
    __shared__ __align__(16) unsigned Bs[2][BK][BSTR];

    const int tid  = threadIdx.x;
    const int lane = tid & 31;
    const int warp = tid >> 5;
    const int g    = lane >> 2;
    const int tig  = lane & 3;
    const int wm   = (warp & 1) * 64;
    const int wn   = (warp >> 1) * 32;

    const int b  = blockIdx.z;
    const int m0 = blockIdx.y * BM;
    const int n0 = blockIdx.x * BN;

    const float* Ap = A + (long)b * sA;
    const float* Bp = B + (long)b * sB;
    float*       Cp = C + (long)b * sC;

    float acc[4][4][4];
#pragma unroll
    for (int i = 0; i < 4; i++)
#pragma unroll
        for (int j = 0; j < 4; j++)
#pragma unroll
            for (int r = 0; r < 4; r++) acc[i][j][r] = 0.f;

    float4 ra0, ra1, rb0, rb1;

    auto loadA = [&](int k0) {
        int m = tid >> 2, kq = (tid & 3) << 2;
        ra0 = *(const float4*)(Ap + (long)(m0 + m)      * lda + k0 + kq);
        ra1 = *(const float4*)(Ap + (long)(m0 + m + 64) * lda + k0 + kq);
    };
    auto loadB = [&](int k0) {
        if (LAYB == 0) {
            int k = tid >> 5, n = (tid & 31) << 2;
            rb0 = *(const float4*)(Bp + (long)(k0 + k)     * ldb + n0 + n);
            rb1 = *(const float4*)(Bp + (long)(k0 + k + 8) * ldb + n0 + n);
        } else {
            int n = tid >> 2, kq = (tid & 3) << 2;
            rb0 = *(const float4*)(Bp + (long)(n0 + n)      * ldb + k0 + kq);
            rb1 = *(const float4*)(Bp + (long)(n0 + n + 64) * ldb + k0 + kq);
        }
    };
    auto storeAB = [&](int buf) {
        int m = tid >> 2, kq = (tid & 3) << 2;
        *(uint4*)&As[buf][m][kq]      = f2tf4(ra0);
        *(uint4*)&As[buf][m + 64][kq] = f2tf4(ra1);
        if (LAYB == 0) {
            int k = tid >> 5, n = (tid & 31) << 2;
            int s0 = ((k >> 2) & 3) << 3;
            int s1 = (((k + 8) >> 2) & 3) << 3;
            *(uint4*)&Bs[buf][k][n ^ s0]     = f2tf4(rb0);
            *(uint4*)&Bs[buf][k + 8][n ^ s1] = f2tf4(rb1);
        } else {
            int n = tid >> 2, q = tid & 3;
            int s  = q << 3;
            int c0 = n ^ s, c1 = (n + 64) ^ s;
            Bs[buf][4 * q + 0][c0] = f2tf(rb0.x);
            Bs[buf][4 * q + 1][c0] = f2tf(rb0.y);
            Bs[buf][4 * q + 2][c0] = f2tf(rb0.z);
            Bs[buf][4 * q + 3][c0] = f2tf(rb0.w);
            Bs[buf][4 * q + 0][c1] = f2tf(rb1.x);
            Bs[buf][4 * q + 1][c1] = f2tf(rb1.y);
            Bs[buf][4 * q + 2][c1] = f2tf(rb1.z);
            Bs[buf][4 * q + 3][c1] = f2tf(rb1.w);
        }
    };
    auto compute = [&](int buf) {
#pragma unroll
        for (int ks = 0; ks < BK; ks += 8) {
            unsigned af[4][4], bfr[4][2];
            const int s0 = ((ks >> 2) & 3) << 3;
            const int s1 = (((ks >> 2) + 1) & 3) << 3;
#pragma unroll
            for (int mi = 0; mi < 4; mi++) {
                int m = wm + mi * 16;
                af[mi][0] = As[buf][m + g]    [ks + tig];
                af[mi][1] = As[buf][m + g + 8][ks + tig];
                af[mi][2] = As[buf][m + g]    [ks + tig + 4];
                af[mi][3] = As[buf][m + g + 8][ks + tig + 4];
            }
#pragma unroll
            for (int ni = 0; ni < 4; ni++) {
                int n = wn + ni * 8 + g;
                bfr[ni][0] = Bs[buf][ks + tig]    [n ^ s0];
                bfr[ni][1] = Bs[buf][ks + tig + 4][n ^ s1];
            }
#pragma unroll
            for (int mi = 0; mi < 4; mi++)
#pragma unroll
                for (int ni = 0; ni < 4; ni++)
                    mma_tf32(acc[mi][ni], af[mi], bfr[ni]);
        }
    };

    const int nt = K / BK;
    loadA(0); loadB(0);
    storeAB(0);
    __syncthreads();
#pragma unroll 1
    for (int t = 0; t < nt; t++) {
        if (t + 1 < nt) { loadA((t + 1) * BK); loadB((t + 1) * BK); }
        compute(t & 1);
        if (t + 1 < nt) storeAB((t + 1) & 1);
        __syncthreads();
    }

    float gam = 0.f;
    const float* Rp = nullptr;
    if (EPI) { gam = gammaPtr[0]; Rp = resid + (long)b * sR; }

#pragma unroll
    for (int mi = 0; mi < 4; mi++) {
#pragma unroll
        for (int ni = 0; ni < 4; ni++) {
            int m = m0 + wm + mi * 16 + g;
            int n = n0 + wn + ni * 8 + 2 * tig;
            float2 v0 = make_float2(acc[mi][ni][0], acc[mi][ni][1]);
            float2 v1 = make_float2(acc[mi][ni][2], acc[mi][ni][3]);
            if (EPI) {
                float2 r0 = *(const float2*)(Rp + (long)m * N + n);
                float2 r1 = *(const float2*)(Rp + (long)(m + 8) * N + n);
                v0.x = fmaf(gam, v0.x, r0.x);
                v0.y = fmaf(gam, v0.y, r0.y);
                v1.x = fmaf(gam, v1.x, r1.x);
                v1.y = fmaf(gam, v1.y, r1.y);
            }
            *(float2*)(Cp + (long)m * N + n)       = v0;
            *(float2*)(Cp + (long)(m + 8) * N + n) = v1;
        }
    }
}

// ---------------------------------------------------------------------------
__global__ void pack_w_kernel(const float* __restrict__ wt,
                              const float* __restrict__ wp,
                              const float* __restrict__ wg)
{
    int i = blockIdx.x * blockDim.x + threadIdx.x;
    if (i >= MPROJ * C_IN) return;
    const int T = 64 * C_IN;
    const int P = 128 * C_IN;
    float v;
    if (i < T)       v = wt[i];
    else if (i < P)  v = wp[i - T];
    else             v = wg[i - P];
    g_Wall[i] = v;
}

// thetaT[b][q][p] = bf16(theta[lam(p)][q])   (64 x 64 tiles via smem)
__global__ __launch_bounds__(256) void theta_prep()
{
    __shared__ float sm[64][65];
    int b = blockIdx.y, q0 = blockIdx.x * 64;
    int tid = threadIdx.x;
    const float* src = g_proj + (long)b * MPROJ * HWX;
#pragma unroll
    for (int i = 0; i < 4; i++) {
        int idx = tid + i * 256;
        int d = idx >> 4, q4 = (idx & 15) * 4;
        float4 v = *(const float4*)(src + (long)d * HWX + q0 + q4);
        sm[d][q4] = v.x; sm[d][q4 + 1] = v.y;
        sm[d][q4 + 2] = v.z; sm[d][q4 + 3] = v.w;
    }
    __syncthreads();
    __nv_bfloat16* dst = g_thetaT + ((long)b * HWX + q0) * CBAR;
#pragma unroll
    for (int i = 0; i < 4; i++) {
        int idx = tid + i * 256;
        int q = idx >> 4, p4 = (idx & 15) * 4;
        *(__nv_bfloat162*)(dst + (long)q * CBAR + p4) =
            __float22bfloat162_rn(make_float2(sm[lam(p4)][q], sm[lam(p4 + 1)][q]));
        *(__nv_bfloat162*)(dst + (long)q * CBAR + p4 + 2) =
            __float22bfloat162_rn(make_float2(sm[lam(p4 + 2)][q], sm[lam(p4 + 3)][q]));
    }
}

// phiT[b][t][p] = bf16(maxpool(phi)[lam(p)][t])
__global__ __launch_bounds__(256) void phi_prep()
{
    __shared__ float sm[64][65];
    int b = blockIdx.y, t0 = blockIdx.x * 64;
    int tid = threadIdx.x;
    const float* src = g_proj + ((long)b * MPROJ + 64) * HWX;
#pragma unroll
    for (int i = 0; i < 16; i++) {
        int idx = tid + i * 256;
        int d = idx >> 6, t = idx & 63;
        int tt = t0 + t, ph = tt >> 5, pw = tt & 31;
        const float* p = src + (long)d * HWX + ph * 128 + 2 * pw;
        sm[d][t] = fmaxf(fmaxf(p[0], p[1]), fmaxf(p[64], p[65]));
    }
    __syncthreads();
    __nv_bfloat16* dst = g_phiT + ((long)b * HW4 + t0) * CBAR;
#pragma unroll
    for (int i = 0; i < 4; i++) {
        int idx = tid + i * 256;
        int t = idx >> 4, p4 = (idx & 15) * 4;
        *(__nv_bfloat162*)(dst + (long)t * CBAR + p4) =
            __float22bfloat162_rn(make_float2(sm[lam(p4)][t], sm[lam(p4 + 1)][t]));
        *(__nv_bfloat162*)(dst + (long)t * CBAR + p4 + 2) =
            __float22bfloat162_rn(make_float2(sm[lam(p4 + 2)][t], sm[lam(p4 + 3)][t]));
    }
}

// g_gbf[b][c][t] = bf16(maxpool(g)[c][t])
__global__ __launch_bounds__(256) void g_prep()
{
    int idx = blockIdx.x * 256 + threadIdx.x;
    int t = idx & 1023;
    int c = (idx >> 10) & 255;
    int b = idx >> 18;
    const float* src = g_proj + ((long)b * MPROJ + 128 + c) * HWX;
    int ph = t >> 5, pw = t & 31;
    const float* p = src + ph * 128 + 2 * pw;
    float m = fmaxf(fmaxf(p[0], p[1]), fmaxf(p[64], p[65]));
    g_gbf[idx] = __float2bfloat16(m);
}

// ---------------------------------------------------------------------------
extern "C" void kernel_launch(void* const* d_in, const int* in_sizes, int n_in,
                              void* d_out, int out_size)
{
    const float* x       = (const float*)d_in[0];
    const float* w_theta = (const float*)d_in[1];
    const float* w_phi   = (const float*)d_in[2];
    const float* w_g     = (const float*)d_in[3];
    const float* w_o     = (const float*)d_in[4];
    const float* gamma   = (const float*)d_in[5];
    float* out = (float*)d_out;

    float *pWall, *pProj, *pYq;
    cudaGetSymbolAddress((void**)&pWall, g_Wall);
    cudaGetSymbolAddress((void**)&pProj, g_proj);
    cudaGetSymbolAddress((void**)&pYq,   g_yq);

    static int smem_set = 0;
    if (!smem_set) {
        cudaFuncSetAttribute(flash_kernel,
                             cudaFuncAttributeMaxDynamicSharedMemorySize,
                             FL_SMEM);
        smem_set = 1;
    }

    // 1. pack weights
    pack_w_kernel<<<(MPROJ * C_IN + 255) / 256, 256>>>(w_theta, w_phi, w_g);

    // 2. proj = W_all @ x : M=384, N=4096, K=512
    {
        dim3 grid(HWX / BN, MPROJ / BM, NB);
        gemm_tc<0, 0><<<grid, 256>>>(pWall, x, pProj,
                                     HWX, C_IN, C_IN, HWX,
                                     0, (long)C_IN * HWX, (long)MPROJ * HWX,
                                     nullptr, nullptr, 0);
    }

    // 3. preps: thetaT / phiT (pooled) / g bf16 (pooled)
    theta_prep<<<dim3(HWX / 64, NB), 256>>>();
    phi_prep<<<dim3(HW4 / 64, NB), 256>>>();
    g_prep<<<(NB * CHAT * HW4) / 256, 256>>>();

    // 4. flash: fused scores -> softmax -> y  (q-major output)
    {
        dim3 grid(HWX / MQF, NB);
        flash_kernel<<<grid, 512, FL_SMEM>>>();
    }

    // 5. out = gamma * (w_o @ y) + x : M=512, N=4096, K=256, B row-major [q][c]
    {
        dim3 grid(HWX / BN, C_IN / BM, NB);
        gemm_tc<1, 1><<<grid, 256>>>(w_o, pYq, out,
                                     HWX, CHAT, CHAT, CHAT,
                                     0, (long)HWX * CHAT, (long)C_IN * HWX,
                                     gamma, x, (long)C_IN * HWX);
    }
}